// round 9
// baseline (speedup 1.0000x reference)
#include <cuda_runtime.h>
#include <cstdint>

#define BB 2
#define TT 512
#define CC 128
#define C2 256
#define HS 64

#define SA 16.0f
#define SB 1024.0f
#define INV_SAB (1.0f / (16.0f * 1024.0f))

// ---------------- scratch (no allocations allowed) -------------------------
__device__ float g_K[BB*TT*CC];
__device__ float g_Q[BB*TT*CC];
__device__ float g_V[BB*TT*HS];
__device__ float g_S[(size_t)BB*TT*TT];
// W1^T (n-major) int8, swizzled 256B rows: 128 n x 256 k = 32KB
__device__ __align__(16) unsigned char g_Bimg[32768];

__device__ __forceinline__ uint32_t smem_u32(const void* p) {
    uint32_t a;
    asm("{ .reg .u64 t; cvta.to.shared.u64 t, %1; cvt.u32.u64 %0, t; }" : "=r"(a) : "l"(p));
    return a;
}
// 256B-row layout, swizzled per 128B half so 8 rows hit distinct 16B banks
__device__ __forceinline__ uint32_t swz256(uint32_t row, uint32_t kb) {
    return row*256u + (kb & 128u) + ((kb & 127u) ^ ((row & 7u)*16u));
}
__host__ __device__ __forceinline__ uint32_t swz256_h(uint32_t row, uint32_t kb) {
    return row*256u + (kb & 128u) + ((kb & 127u) ^ ((row & 7u)*16u));
}

__device__ __forceinline__ void ldsm_x4(uint32_t addr, uint32_t& r0, uint32_t& r1,
                                        uint32_t& r2, uint32_t& r3) {
    asm volatile("ldmatrix.sync.aligned.m8n8.x4.shared.b16 {%0,%1,%2,%3}, [%4];"
                 : "=r"(r0), "=r"(r1), "=r"(r2), "=r"(r3) : "r"(addr));
}
__device__ __forceinline__ void imma16832(int* d, const uint32_t* a, uint32_t b0, uint32_t b1) {
    asm volatile("mma.sync.aligned.m16n8k32.row.col.s32.s8.s8.s32 "
                 "{%0,%1,%2,%3}, {%4,%5,%6,%7}, {%8,%9}, {%0,%1,%2,%3};"
                 : "+r"(d[0]), "+r"(d[1]), "+r"(d[2]), "+r"(d[3])
                 : "r"(a[0]), "r"(a[1]), "r"(a[2]), "r"(a[3]), "r"(b0), "r"(b1));
}
__device__ __forceinline__ uint32_t quant4(float4 v, float s) {
    int a0 = __float2int_rn(fminf(fmaxf(v.x*s, -127.f), 127.f));
    int a1 = __float2int_rn(fminf(fmaxf(v.y*s, -127.f), 127.f));
    int a2 = __float2int_rn(fminf(fmaxf(v.z*s, -127.f), 127.f));
    int a3 = __float2int_rn(fminf(fmaxf(v.w*s, -127.f), 127.f));
    return (uint32_t)(a0 & 255) | ((uint32_t)(a1 & 255) << 8)
         | ((uint32_t)(a2 & 255) << 16) | ((uint32_t)(a3 & 255) << 24);
}
// exact gelu via erff (cheap polynomial, no exp path)
__device__ __forceinline__ float gelu_exact(float x) {
    return 0.5f * x * (1.f + erff(x * 0.70710678118654752f));
}

// ---------------------------------------------------------------------------
// Kernel 0: W1 -> W1^T int8 swizzled image (scale SB)
// ---------------------------------------------------------------------------
__global__ void prepB_kernel(const float* __restrict__ W1) {
    int t = blockIdx.x * 256 + threadIdx.x;   // 0 .. 32767
    if (t >= 128*256) return;
    int n = t >> 8;
    int k = t & 255;
    float w = W1[k*CC + n];
    int q = __float2int_rn(fminf(fmaxf(w * SB, -127.f), 127.f));
    g_Bimg[swz256((uint32_t)n, (uint32_t)k)] = (unsigned char)(q & 255);
}

// ---------------------------------------------------------------------------
// Kernel 1: K/Q/V.  4 rows per block, 256 threads, 256 blocks.
// ---------------------------------------------------------------------------
__global__ void kqv_kernel(const float* __restrict__ x,
                           const float* __restrict__ W1,
                           const float* __restrict__ Wv,
                           const float* __restrict__ bv) {
    __shared__ float sx[4][CC];
    int r0 = blockIdx.x * 4;
    int t = threadIdx.x;
    for (int idx = t; idx < 4*CC; idx += 256)
        sx[idx >> 7][idx & 127] = x[(r0 + (idx >> 7))*CC + (idx & 127)];
    __syncthreads();

    int h = t & 127;
    const float* Wcol = (t < 128) ? W1 : (W1 + CC*CC);
    float a[4] = {0.f, 0.f, 0.f, 0.f};
#pragma unroll 8
    for (int d = 0; d < CC; d++) {
        float w = Wcol[d*CC + h];
#pragma unroll
        for (int r = 0; r < 4; r++) a[r] = fmaf(sx[r][d], w, a[r]);
    }
    float* dst = (t < 128) ? g_K : g_Q;
#pragma unroll
    for (int r = 0; r < 4; r++) dst[(r0 + r)*CC + h] = a[r];

    if (t < HS) {
        float v[4];
        float bvh = bv[t];
#pragma unroll
        for (int r = 0; r < 4; r++) v[r] = bvh;
#pragma unroll 8
        for (int d = 0; d < CC; d++) {
            float w = Wv[d*HS + t];
#pragma unroll
            for (int r = 0; r < 4; r++) v[r] = fmaf(sx[r][d], w, v[r]);
        }
#pragma unroll
        for (int r = 0; r < 4; r++) g_V[(r0 + r)*HS + t] = v[r];
    }
}

// ---------------------------------------------------------------------------
// Kernel 2: int8 IMMA (m16n8k32) P-GEMM + erff gelu epilogue
//   block = (i, 64-j tile), 128 threads = 4 warps, warp 16j x 128n
// smem: [0,32K) B image  [32K,48K) A tile (64 x 256B s8)  [48K..) misc
// ---------------------------------------------------------------------------
#define A_OFF 32768
#define MISC  49152
#define SMEM_BYTES (MISC + 2048)

__global__ void __launch_bounds__(128, 4)
score_kernel(const float* __restrict__ pd,
             const float* __restrict__ b1,
             const float* __restrict__ W2,
             const float* __restrict__ b2) {
    int i = blockIdx.x;
    int jbase = blockIdx.y * 64;
    if (jbase > i) return;
    int jmax = (i - jbase < 64) ? (i - jbase) : 63;

    extern __shared__ __align__(16) unsigned char sm[];
    uint32_t base = smem_u32(sm);

    int tid  = threadIdx.x;
    int lane = tid & 31;
    int wid  = tid >> 5;          // 4 warps, each 16 j-rows
    int j0   = wid * 16;
    bool active = (j0 <= jmax);

    float* w2s = (float*)(sm + MISC);          // 128 f
    float* qs  = (float*)(sm + MISC + 512);    // 2 x 128 f
    float b2v  = b2[0];

    if (tid < 128) {
        w2s[tid] = W2[tid];
        float b1h = b1[tid];
        qs[tid]       = g_Q[((size_t)i)*CC + tid]        + b1h;
        qs[128 + tid] = g_Q[((size_t)(TT + i))*CC + tid] + b1h;
    }
    {   // B image -> smem (32KB)
        const float4* src = (const float4*)g_Bimg;
        float4* dst = (float4*)sm;
#pragma unroll
        for (int it = 0; it < 16; it++) dst[tid + it*128] = src[tid + it*128];
    }
    {   // A tile: 64 j x 256 k fp32 -> s8, swizzled
        const float4* prow = (const float4*)(pd + ((size_t)i*TT + jbase)*C2);
#pragma unroll 8
        for (int it = 0; it < 32; it++) {
            int idx = tid + it*128;        // 0..4095
            int j   = idx >> 6;
            int f4  = idx & 63;
            if (j <= jmax) {
                float4 v = prow[j*64 + f4];
                *(uint32_t*)(sm + A_OFF + swz256((uint32_t)j, (uint32_t)f4*4u)) =
                    quant4(v, SA);
            }
        }
    }
    __syncthreads();

    int acc[16][4];
#pragma unroll
    for (int nt = 0; nt < 16; nt++)
#pragma unroll
        for (int r = 0; r < 4; r++) acc[nt][r] = 0;

    if (active) {
#pragma unroll
        for (int ks = 0; ks < 8; ks++) {
            uint32_t kb = (uint32_t)ks*32u;
            uint32_t a[4];
            ldsm_x4(base + A_OFF + swz256((uint32_t)(j0 + (lane & 15)),
                                          kb + ((uint32_t)(lane >> 4))*16u),
                    a[0], a[1], a[2], a[3]);
#pragma unroll
            for (int p = 0; p < 8; p++) {
                uint32_t n  = (uint32_t)(p*16 + (lane & 7) + ((lane >> 4) << 3));
                uint32_t by = kb + ((uint32_t)((lane >> 3) & 1))*16u;
                uint32_t b0, b1r, b2r, b3;
                ldsm_x4(base + swz256(n, by), b0, b1r, b2r, b3);
                imma16832(acc[2*p],     a, b0,  b1r);
                imma16832(acc[2*p + 1], a, b2r, b3);
            }
        }

        // --- epilogue: dequant + q + k, erff gelu, W2 dot, quad reduce
#pragma unroll
        for (int b = 0; b < BB; b++) {
            const float* qb = qs + b*128;
#pragma unroll
            for (int rh = 0; rh < 2; rh++) {
                int j = j0 + (lane >> 2) + 8*rh;
                const float* kb = g_K + ((size_t)(b*TT + jbase + j))*CC;
                float partial = 0.f;
#pragma unroll
                for (int nt = 0; nt < 16; nt++) {
                    int h0 = nt*8 + (lane & 3)*2;
                    float2 kv = *(const float2*)(kb + h0);
                    float pre0 = (float)acc[nt][rh*2 + 0] * INV_SAB + qb[h0]     + kv.x;
                    float pre1 = (float)acc[nt][rh*2 + 1] * INV_SAB + qb[h0 + 1] + kv.y;
                    partial = fmaf(gelu_exact(pre0), w2s[h0],     partial);
                    partial = fmaf(gelu_exact(pre1), w2s[h0 + 1], partial);
                }
                partial += __shfl_xor_sync(0xffffffffu, partial, 1);
                partial += __shfl_xor_sync(0xffffffffu, partial, 2);
                int jg = jbase + j;
                if ((lane & 3) == 0 && jg <= i)
                    g_S[((size_t)(b*TT + i))*TT + jg] = partial + b2v;
            }
        }
    }
}

// ---------------------------------------------------------------------------
// Kernel 3: causal softmax (scaled) + wei @ V, 256 threads
// ---------------------------------------------------------------------------
__global__ void softmax_av_kernel(float* __restrict__ out) {
    int bi = blockIdx.x;
    int b = bi >> 9, i = bi & 511;
    int t = threadIdx.x;
    int n = i + 1;

    __shared__ float p[TT];
    __shared__ float red[256];
    const float scale = 0.088388347648318447f;
    const float* srow = &g_S[((size_t)(b*TT + i))*TT];

    float m = -1e30f;
    for (int j = t; j < n; j += 256) m = fmaxf(m, srow[j]*scale);
    red[t] = m; __syncthreads();
    for (int s = 128; s; s >>= 1) { if (t < s) red[t] = fmaxf(red[t], red[t+s]); __syncthreads(); }
    m = red[0]; __syncthreads();

    float sum = 0.f;
    for (int j = t; j < n; j += 256) {
        float e = expf(srow[j]*scale - m);
        p[j] = e;
        sum += e;
    }
    red[t] = sum; __syncthreads();
    for (int s = 128; s; s >>= 1) { if (t < s) red[t] += red[t+s]; __syncthreads(); }
    float inv = 1.f / red[0];
    __syncthreads();

    int h = t & 63, slice = t >> 6;
    float acc = 0.f;
    for (int j = slice; j < n; j += 4)
        acc = fmaf(p[j], g_V[((size_t)(b*TT + j))*HS + h], acc);
    red[t] = acc; __syncthreads();
    if (t < HS)
        out[((size_t)(b*TT + i))*HS + t] =
            (red[t] + red[t+64] + red[t+128] + red[t+192]) * inv;
}

// ---------------------------------------------------------------------------
extern "C" void kernel_launch(void* const* d_in, const int* in_sizes, int n_in,
                              void* d_out, int out_size) {
    const float* x  = (const float*)d_in[0];
    const float* pd = (const float*)d_in[2];
    const float* W1 = (const float*)d_in[3];
    const float* b1 = (const float*)d_in[4];
    const float* W2 = (const float*)d_in[5];
    const float* b2 = (const float*)d_in[6];
    const float* Wv = (const float*)d_in[7];
    const float* bv = (const float*)d_in[8];
    float* out = (float*)d_out;

    cudaFuncSetAttribute(score_kernel, cudaFuncAttributeMaxDynamicSharedMemorySize, SMEM_BYTES);

    prepB_kernel<<<128, 256>>>(W1);
    kqv_kernel<<<256, 256>>>(x, W1, Wv, bv);
    score_kernel<<<dim3(TT, 8), 128, SMEM_BYTES>>>(pd, b1, W2, b2);
    softmax_av_kernel<<<BB*TT, 256>>>(out);
}